// round 12
// baseline (speedup 1.0000x reference)
#include <cuda_runtime.h>
#include <math.h>

#define NMAX   2048
#define CB     32            // 64-wide bit blocks -> supports up to 2048 boxes
#define TPB    64            // threads (=rows) per tile
#define TILES_PER_BLOCK 2
#define BLOCK  (TPB * TILES_PER_BLOCK)      // 128
#define MAXPAIRS (TILES_PER_BLOCK * TPB * TPB)  // 8192: provable per-block max
#define RTPB   1024
#define FEPS   1e-8f
#define THRESH 0.7f
#define FULLM  0xffffffffu

// scratch (device globals: no allocation allowed; zero-init at load,
// restored to zero by reduce_kernel's epilogue each run => replay-safe)
__device__ unsigned long long g_maskT[NMAX * CB]; // maskT[j] bit i: box i (<j) suppresses j
__device__ unsigned int g_colsum[NMAX];           // bit blk set iff maskT row j has bits in i-block blk

// ---------------------------------------------------------------------------
// Sutherland-Hodgman: area of intersection of two convex CCW quads.
// ---------------------------------------------------------------------------
__device__ float sh_inter(const float* __restrict__ px, const float* __restrict__ py,
                          const float* __restrict__ qx, const float* __restrict__ qy) {
    float ax[12], ay[12], bx[12], by[12];
#pragma unroll
    for (int k = 0; k < 4; k++) { ax[k] = px[k]; ay[k] = py[k]; }
    int m = 4;
    float *cxv = ax, *cyv = ay, *nxv = bx, *nyv = by;
#pragma unroll
    for (int l = 0; l < 4; l++) {
        int l1 = (l + 1) & 3;
        float ex = qx[l1] - qx[l], ey = qy[l1] - qy[l];
        float ox = qx[l],         oy = qy[l];
        int nm = 0;
        float pxv = cxv[m - 1], pyv = cyv[m - 1];
        float ps = ex * (pyv - oy) - ey * (pxv - ox);
        for (int v = 0; v < m; v++) {
            float cx = cxv[v], cy = cyv[v];
            float cs = ex * (cy - oy) - ey * (cx - ox);
            if (cs >= 0.f) {
                if (ps < 0.f) {
                    float t = ps / (ps - cs);
                    nxv[nm] = pxv + t * (cx - pxv);
                    nyv[nm] = pyv + t * (cy - pyv);
                    nm++;
                }
                nxv[nm] = cx; nyv[nm] = cy; nm++;
            } else if (ps >= 0.f) {
                float t = ps / (ps - cs);
                nxv[nm] = pxv + t * (cx - pxv);
                nyv[nm] = pyv + t * (cy - pyv);
                nm++;
            }
            pxv = cx; pyv = cy; ps = cs;
        }
        m = nm;
        if (m == 0) return 0.f;
        float* t1 = cxv; cxv = nxv; nxv = t1;
        float* t2 = cyv; cyv = nyv; nyv = t2;
    }
    if (m < 3) return 0.f;
    float area = 0.f;
    int prev = m - 1;
    for (int v = 0; v < m; v++) {
        area += cxv[prev] * cyv[v] - cxv[v] * cyv[prev];
        prev = v;
    }
    return 0.5f * fabsf(area);
}

__device__ __forceinline__ void make_corners(const float* __restrict__ b, int i,
                                             float* px, float* py) {
    float xc = b[i * 5 + 0], yc = b[i * 5 + 1];
    float w  = b[i * 5 + 2], h  = b[i * 5 + 3];
    float th = b[i * 5 + 4] * (float)(M_PI / 180.0);
    float c = cosf(th), s = sinf(th);
    const float lx[4] = {0.5f, -0.5f, -0.5f, 0.5f};
    const float ly[4] = {0.5f, 0.5f, -0.5f, -0.5f};
#pragma unroll
    for (int k = 0; k < 4; k++) {
        px[k] = xc + lx[k] * w * c - ly[k] * h * s;
        py[k] = yc + lx[k] * w * s + ly[k] * h * c;
    }
}

// ---------------------------------------------------------------------------
// Kernel 1 (fused filter+clip): flattened upper-tri tile grid, 2 tiles/block.
// Phase 1: exact-safe rejects (area ratio + bounding circles) -> 64-bit hit
//          words -> warp-aggregated push into a SHARED pair list (cap 8192 =
//          hard upper bound, no overflow possible).
// Phase 2: after one barrier, the whole block SH-clips its own pairs.
// Writes transposed suppression matrix via atomicOr (deterministic).
// ---------------------------------------------------------------------------
__global__ void pairs_kernel(const float* __restrict__ boxes, int n,
                             int rb, int ntiles) {
    __shared__ float4 smeta[BLOCK];          // per-tile column metadata
    __shared__ unsigned s_pairs[MAXPAIRS];   // 32KB
    __shared__ int s_cnt;

    const int tid = threadIdx.x;
    if (tid == 0) s_cnt = 0;
    const int sub = tid >> 6;                // tile slot in block
    const int t   = tid & 63;
    const int tile = blockIdx.x * TILES_PER_BLOCK + sub;
    const bool tilevalid = (tile < ntiles);

    // decode flattened upper-tri tile id -> (rowb, colb), colb >= rowb
    int rowb = 0, colb = 0;
    if (tilevalid) {
        int k = tile;
        int tw = 2 * rb + 1;
        int r = (int)(((float)tw - sqrtf((float)(tw * tw - 8 * k))) * 0.5f);
        if (r < 0) r = 0;
        if (r >= rb) r = rb - 1;
        while (r + 1 < rb && ((r + 1) * rb - ((r + 1) * r) / 2) <= k) r++;
        while (r > 0 && (r * rb - (r * (r - 1)) / 2) > k) r--;
        rowb = r;
        colb = r + (k - (r * rb - (r * (r - 1)) / 2));
    }
    const int col0 = colb * TPB;
    const int row  = rowb * TPB + t;

    // stage this tile's column metadata (cx, cy, area, r)
    {
        int j = col0 + t;
        if (tilevalid && j < n) {
            float w = boxes[j * 5 + 2], h = boxes[j * 5 + 3];
            smeta[sub * TPB + t] = make_float4(boxes[j * 5 + 0], boxes[j * 5 + 1],
                                               w * h, 0.5f * sqrtf(w * w + h * h));
        } else {
            smeta[sub * TPB + t] = make_float4(3e30f, 3e30f, 0.f, 0.f); // never hits
        }
    }
    __syncthreads();

    // phase 1: filter
    const bool rowvalid = tilevalid && (row < n);
    const int rload = rowvalid ? row : 0;
    const float wR = boxes[rload * 5 + 2], hR = boxes[rload * 5 + 3];
    const float ai  = wR * hR;
    const float cxi = boxes[rload * 5 + 0], cyi = boxes[rload * 5 + 1];
    const float ri  = 0.5f * sqrtf(wR * wR + hR * hR);

    unsigned long long hits = 0ULL;
#pragma unroll 4
    for (int jj = 0; jj < TPB; jj++) {
        float4 mj = smeta[sub * TPB + jj];
        float amin = fminf(ai, mj.z), amax = fmaxf(ai, mj.z);
        float dx = cxi - mj.x, dy = cyi - mj.y;
        float rr = ri + mj.w;
        bool hit = (amin > THRESH * amax) && (dx * dx + dy * dy < rr * rr);
        hits |= ((unsigned long long)hit) << jj;
    }
    if (!rowvalid) hits = 0ULL;
    if (colb == rowb)
        hits &= (t >= 63) ? 0ULL : ~((2ULL << t) - 1ULL);   // strictly upper

    // warp-aggregated push into the shared pair list
    const int lane = tid & 31;
    unsigned c = (unsigned)__popcll(hits);
    unsigned sc = c;
#pragma unroll
    for (int d = 1; d < 32; d <<= 1) {
        unsigned v = __shfl_up_sync(FULLM, sc, d);
        if (lane >= d) sc += v;
    }
    unsigned wtot = __shfl_sync(FULLM, sc, 31);
    int base = 0;
    if (lane == 31 && wtot) base = atomicAdd(&s_cnt, (int)wtot);
    base = __shfl_sync(FULLM, base, 31);
    int off = base + (int)(sc - c);
    while (hits) {
        int jj = __ffsll(hits) - 1;
        hits &= hits - 1;
        s_pairs[off++] = ((unsigned)row << 11) | (unsigned)(col0 + jj);
    }
    __syncthreads();

    // phase 2: clip this block's pairs
    const int cnt = s_cnt;
    for (int p = tid; p < cnt; p += BLOCK) {
        unsigned pr = s_pairs[p];
        int i = (int)(pr >> 11);
        int j = (int)(pr & 2047u);
        float px[4], py[4], qx[4], qy[4];
        make_corners(boxes, i, px, py);
        make_corners(boxes, j, qx, qy);
        float inter = sh_inter(px, py, qx, qy);
        float aiA = boxes[i * 5 + 2] * boxes[i * 5 + 3];
        float ajA = boxes[j * 5 + 2] * boxes[j * 5 + 3];
        float iou = inter / fmaxf(aiA + ajA - inter, FEPS);
        if (iou > THRESH) {
            int blk = i >> 6;
            atomicOr(&g_maskT[(size_t)j * CB + blk], 1ULL << (i & 63));
            atomicOr(&g_colsum[j], 1u << blk);
        }
    }
}

// ---------------------------------------------------------------------------
// Kernel 2: parallel Jacobi fixpoint of the greedy recurrence.
//   keep[j] = (j<n) && !exists i<j: keep[i] && M[i][j]
// Register-cached maskT words (first 2 per row; global fallback). Epilogue
// restores maskT/colsum to zero for the next graph replay.
// ---------------------------------------------------------------------------
__global__ void reduce_kernel(int n, float* __restrict__ out, int out_size) {
    __shared__ unsigned s_kept[64];
    __shared__ unsigned s_pref[64];
    __shared__ int s_changed[2];
    __shared__ int s_total;
    const int tid = threadIdx.x;
    const int j0 = tid, j1 = tid + RTPB;

    if (tid == 0) { s_changed[0] = 0; s_changed[1] = 0; }

    if (tid < 64) {
        int base = tid * 32;
        unsigned w = 0u;
        if (base + 32 <= n) w = FULLM;
        else if (base < n) w = (1u << (n - base)) - 1u;
        s_kept[tid] = w;
    }

    const unsigned cs0 = (j0 < n) ? g_colsum[j0] : 0u;
    const unsigned cs1 = (j1 < n) ? g_colsum[j1] : 0u;

    // register-cache first two maskT words per row
    unsigned long long A0 = 0, A1 = 0, B0 = 0, B1 = 0;
    int ab0 = -1, ab1 = -1, bb0 = -1, bb1 = -1;
    unsigned rest0 = 0, rest1 = 0;
    {
        unsigned s = cs0;
        if (s) { ab0 = __ffs(s) - 1; A0 = g_maskT[(size_t)j0 * CB + ab0]; s &= s - 1;
            if (s) { ab1 = __ffs(s) - 1; A1 = g_maskT[(size_t)j0 * CB + ab1]; s &= s - 1; }
            rest0 = s;
        }
        s = cs1;
        if (s) { bb0 = __ffs(s) - 1; B0 = g_maskT[(size_t)j1 * CB + bb0]; s &= s - 1;
            if (s) { bb1 = __ffs(s) - 1; B1 = g_maskT[(size_t)j1 * CB + bb1]; s &= s - 1; }
            rest1 = s;
        }
    }
    __syncthreads();

    int cur = 0;
    for (int iter = 0; iter < n; iter++) {
        bool k0, k1;
        {
            bool sup = false;
            if (ab0 >= 0) {
                unsigned long long kw = ((unsigned long long)s_kept[ab0 * 2 + 1] << 32)
                                        | (unsigned long long)s_kept[ab0 * 2];
                sup = (A0 & kw) != 0ULL;
            }
            if (!sup && ab1 >= 0) {
                unsigned long long kw = ((unsigned long long)s_kept[ab1 * 2 + 1] << 32)
                                        | (unsigned long long)s_kept[ab1 * 2];
                sup = (A1 & kw) != 0ULL;
            }
            unsigned s = rest0;
            while (!sup && s) {
                int blk = __ffs(s) - 1; s &= s - 1;
                unsigned long long m = g_maskT[(size_t)j0 * CB + blk];
                unsigned long long kw = ((unsigned long long)s_kept[blk * 2 + 1] << 32)
                                        | (unsigned long long)s_kept[blk * 2];
                sup = (m & kw) != 0ULL;
            }
            k0 = (j0 < n) && !sup;
        }
        {
            bool sup = false;
            if (bb0 >= 0) {
                unsigned long long kw = ((unsigned long long)s_kept[bb0 * 2 + 1] << 32)
                                        | (unsigned long long)s_kept[bb0 * 2];
                sup = (B0 & kw) != 0ULL;
            }
            if (!sup && bb1 >= 0) {
                unsigned long long kw = ((unsigned long long)s_kept[bb1 * 2 + 1] << 32)
                                        | (unsigned long long)s_kept[bb1 * 2];
                sup = (B1 & kw) != 0ULL;
            }
            unsigned s = rest1;
            while (!sup && s) {
                int blk = __ffs(s) - 1; s &= s - 1;
                unsigned long long m = g_maskT[(size_t)j1 * CB + blk];
                unsigned long long kw = ((unsigned long long)s_kept[blk * 2 + 1] << 32)
                                        | (unsigned long long)s_kept[blk * 2];
                sup = (m & kw) != 0ULL;
            }
            k1 = (j1 < n) && !sup;
        }
        __syncthreads();   // all reads of s_kept done
        unsigned b0 = __ballot_sync(FULLM, k0);
        unsigned b1 = __ballot_sync(FULLM, k1);
        int w = tid >> 5;
        if ((tid & 31) == 0) {
            if (s_kept[w] != b0)      { s_kept[w] = b0;      s_changed[cur] = 1; }
            if (s_kept[32 + w] != b1) { s_kept[32 + w] = b1; s_changed[cur] = 1; }
        }
        if (tid == 0) s_changed[cur ^ 1] = 0;   // pre-clear next flag
        __syncthreads();   // writes visible
        if (!s_changed[cur]) break;
        cur ^= 1;
    }

    // ---- emit ----
    if (tid == 0) {
        int acc = 0;
        for (int w = 0; w < 64; w++) { s_pref[w] = acc; acc += __popc(s_kept[w]); }
        s_total = acc;
    }
    __syncthreads();
    const int total = s_total;

#pragma unroll
    for (int rr = 0; rr < 2; rr++) {
        int j = tid + rr * RTPB;
        if (j < n) {
            unsigned w = s_kept[j >> 5];
            if ((w >> (j & 31)) & 1u) {
                int rank = (int)s_pref[j >> 5] + __popc(w & ((1u << (j & 31)) - 1u));
                if (rank < out_size) out[rank] = (float)j;
            }
        }
    }
    for (int k = total + tid; k < out_size; k += RTPB) out[k] = -1.0f;

    // ---- epilogue: restore scratch state to zero for next replay ----
    {
        unsigned s = cs0;
        while (s) { int blk = __ffs(s) - 1; s &= s - 1;
                    g_maskT[(size_t)j0 * CB + blk] = 0ULL; }
        if (j0 < n) g_colsum[j0] = 0u;
        s = cs1;
        while (s) { int blk = __ffs(s) - 1; s &= s - 1;
                    g_maskT[(size_t)j1 * CB + blk] = 0ULL; }
        if (j1 < n) g_colsum[j1] = 0u;
    }
}

// ---------------------------------------------------------------------------
extern "C" void kernel_launch(void* const* d_in, const int* in_sizes, int n_in,
                              void* d_out, int out_size) {
    const float* boxes = (const float*)d_in[0];
    int n = in_sizes[0] / 5;

    int rb = (n + TPB - 1) / TPB;          // 32 for n=2000
    int ntiles = rb * (rb + 1) / 2;        // 528
    int nblocks = (ntiles + TILES_PER_BLOCK - 1) / TILES_PER_BLOCK;  // 264

    pairs_kernel<<<nblocks, BLOCK>>>(boxes, n, rb, ntiles);

    reduce_kernel<<<1, RTPB>>>(n, (float*)d_out, out_size);
}

// round 13
// speedup vs baseline: 1.2670x; 1.2670x over previous
#include <cuda_runtime.h>
#include <math.h>

#define NMAX   2048
#define CB     32            // 64-wide bit blocks -> supports up to 2048 boxes
#define TPB    64            // rows per tile
#define TILES_PER_BLOCK 4
#define FBLOCK (TPB * TILES_PER_BLOCK)   // 256
#define RTPB   1024
#define FEPS   1e-8f
#define THRESH 0.7f
#define CAP    (NMAX * NMAX / 2)
#define FULLM  0xffffffffu

// scratch (device globals: no allocation allowed; zero-init at load,
// restored to zero by reduce_kernel each run => replay-safe)
__device__ unsigned long long g_maskT[NMAX * CB]; // maskT[j] bit i: box i (<j) suppresses j
__device__ unsigned int g_colsum[NMAX];           // bit blk set iff maskT row j has bits in i-block blk
__device__ unsigned int g_work[CAP];              // packed pairs: (i << 11) | j
__device__ float4 g_cnr[NMAX * 2];                // corners: (x0,y0,x1,y1),(x2,y2,x3,y3)
__device__ int g_count;                           // reset by reduce_kernel each run

// ---------------------------------------------------------------------------
// Kernel 1 (filter v4): flattened upper-tri tile grid (no dead blocks),
// 4 tiles per 256-thread block. Per-tile float4 smem metadata; diagonal
// tiles also compute+store each row's corners (exactly once). Survivors
// pushed to the GLOBAL worklist (warp scan + 1 atomic/warp) -> the separate
// clip kernel stays perfectly load-balanced.
// ---------------------------------------------------------------------------
__global__ void filter_kernel(const float* __restrict__ boxes, int n,
                              int rb, int ntiles) {
    __shared__ float4 smeta[FBLOCK];   // (cx, cy, area, r) per tile column

    const int tid = threadIdx.x;
    const int sub = tid >> 6;          // tile slot 0..3
    const int t   = tid & 63;
    const int tile = blockIdx.x * TILES_PER_BLOCK + sub;
    const bool tilevalid = (tile < ntiles);

    // decode flattened upper-tri tile id -> (rowb, colb), colb >= rowb
    int rowb = 0, colb = 0;
    if (tilevalid) {
        int k = tile;
        int tw = 2 * rb + 1;
        int r = (int)(((float)tw - sqrtf((float)(tw * tw - 8 * k))) * 0.5f);
        if (r < 0) r = 0;
        if (r >= rb) r = rb - 1;
        while (r + 1 < rb && ((r + 1) * rb - ((r + 1) * r) / 2) <= k) r++;
        while (r > 0 && (r * rb - (r * (r - 1)) / 2) > k) r--;
        rowb = r;
        colb = r + (k - (r * rb - (r * (r - 1)) / 2));
    }
    const int col0 = colb * TPB;
    const int row  = rowb * TPB + t;

    // stage this tile's column metadata
    {
        int j = col0 + t;
        if (tilevalid && j < n) {
            float w = boxes[j * 5 + 2], h = boxes[j * 5 + 3];
            smeta[sub * TPB + t] = make_float4(boxes[j * 5 + 0], boxes[j * 5 + 1],
                                               w * h, 0.5f * sqrtf(w * w + h * h));
        } else {
            smeta[sub * TPB + t] = make_float4(3e30f, 3e30f, 0.f, 0.f); // never hits
        }
    }
    // diagonal tiles compute corners for their rows (each row exactly once)
    if (tilevalid && colb == rowb && row < n) {
        float xc = boxes[row * 5 + 0], yc = boxes[row * 5 + 1];
        float w  = boxes[row * 5 + 2], h  = boxes[row * 5 + 3];
        float th = boxes[row * 5 + 4] * (float)(M_PI / 180.0);
        float c = cosf(th), s = sinf(th);
        const float lx[4] = {0.5f, -0.5f, -0.5f, 0.5f};
        const float ly[4] = {0.5f, 0.5f, -0.5f, -0.5f};
        float px[4], py[4];
#pragma unroll
        for (int k = 0; k < 4; k++) {
            px[k] = xc + lx[k] * w * c - ly[k] * h * s;
            py[k] = yc + lx[k] * w * s + ly[k] * h * c;
        }
        g_cnr[row * 2 + 0] = make_float4(px[0], py[0], px[1], py[1]);
        g_cnr[row * 2 + 1] = make_float4(px[2], py[2], px[3], py[3]);
    }
    __syncthreads();

    const bool rowvalid = tilevalid && (row < n);
    const int rload = rowvalid ? row : 0;
    const float wR = boxes[rload * 5 + 2], hR = boxes[rload * 5 + 3];
    const float ai  = wR * hR;
    const float cxi = boxes[rload * 5 + 0], cyi = boxes[rload * 5 + 1];
    const float ri  = 0.5f * sqrtf(wR * wR + hR * hR);

    unsigned long long hits = 0ULL;
#pragma unroll 4
    for (int jj = 0; jj < TPB; jj++) {
        float4 mj = smeta[sub * TPB + jj];
        float amin = fminf(ai, mj.z), amax = fmaxf(ai, mj.z);
        float dx = cxi - mj.x, dy = cyi - mj.y;
        float rr = ri + mj.w;
        bool hit = (amin > THRESH * amax) && (dx * dx + dy * dy < rr * rr);
        hits |= ((unsigned long long)hit) << jj;
    }
    if (!rowvalid) hits = 0ULL;
    if (colb == rowb)
        hits &= (t >= 63) ? 0ULL : ~((2ULL << t) - 1ULL);   // strictly upper

    // warp-aggregated push to the global worklist
    const int lane = tid & 31;
    unsigned c = (unsigned)__popcll(hits);
    unsigned sc = c;
#pragma unroll
    for (int d = 1; d < 32; d <<= 1) {
        unsigned v = __shfl_up_sync(FULLM, sc, d);
        if (lane >= d) sc += v;
    }
    unsigned wtot = __shfl_sync(FULLM, sc, 31);
    int base = 0;
    if (lane == 31 && wtot) base = atomicAdd(&g_count, (int)wtot);
    base = __shfl_sync(FULLM, base, 31);
    int off = base + (int)(sc - c);
    while (hits) {
        int jj = __ffsll(hits) - 1;
        hits &= hits - 1;
        if (off < CAP)
            g_work[off] = ((unsigned)row << 11) | (unsigned)(col0 + jj);
        off++;
    }
}

// ---------------------------------------------------------------------------
// Sutherland-Hodgman: area of intersection of two convex CCW quads.
// ---------------------------------------------------------------------------
__device__ float sh_inter(const float* __restrict__ px, const float* __restrict__ py,
                          const float* __restrict__ qx, const float* __restrict__ qy) {
    float ax[12], ay[12], bx[12], by[12];
#pragma unroll
    for (int k = 0; k < 4; k++) { ax[k] = px[k]; ay[k] = py[k]; }
    int m = 4;
    float *cxv = ax, *cyv = ay, *nxv = bx, *nyv = by;
#pragma unroll
    for (int l = 0; l < 4; l++) {
        int l1 = (l + 1) & 3;
        float ex = qx[l1] - qx[l], ey = qy[l1] - qy[l];
        float ox = qx[l],         oy = qy[l];
        int nm = 0;
        float pxv = cxv[m - 1], pyv = cyv[m - 1];
        float ps = ex * (pyv - oy) - ey * (pxv - ox);
        for (int v = 0; v < m; v++) {
            float cx = cxv[v], cy = cyv[v];
            float cs = ex * (cy - oy) - ey * (cx - ox);
            if (cs >= 0.f) {
                if (ps < 0.f) {
                    float t = ps / (ps - cs);
                    nxv[nm] = pxv + t * (cx - pxv);
                    nyv[nm] = pyv + t * (cy - pyv);
                    nm++;
                }
                nxv[nm] = cx; nyv[nm] = cy; nm++;
            } else if (ps >= 0.f) {
                float t = ps / (ps - cs);
                nxv[nm] = pxv + t * (cx - pxv);
                nyv[nm] = pyv + t * (cy - pyv);
                nm++;
            }
            pxv = cx; pyv = cy; ps = cs;
        }
        m = nm;
        if (m == 0) return 0.f;
        float* t1 = cxv; cxv = nxv; nxv = t1;
        float* t2 = cyv; cyv = nyv; nyv = t2;
    }
    if (m < 3) return 0.f;
    float area = 0.f;
    int prev = m - 1;
    for (int v = 0; v < m; v++) {
        area += cxv[prev] * cyv[v] - cxv[v] * cyv[prev];
        prev = v;
    }
    return 0.5f * fabsf(area);
}

// ---------------------------------------------------------------------------
// Kernel 2: exact clip, one thread per surviving pair (grid-stride,
// perfectly load-balanced). Corners loaded as float4 pairs.
// ---------------------------------------------------------------------------
__global__ void clip_kernel(const float* __restrict__ boxes) {
    int cnt = g_count;
    if (cnt > CAP) cnt = CAP;
    const int stride = gridDim.x * blockDim.x;
    for (int k = blockIdx.x * blockDim.x + threadIdx.x; k < cnt; k += stride) {
        unsigned p = g_work[k];
        int i = (int)(p >> 11);
        int j = (int)(p & 2047u);
        float4 a0 = g_cnr[i * 2 + 0], a1 = g_cnr[i * 2 + 1];
        float4 b0 = g_cnr[j * 2 + 0], b1 = g_cnr[j * 2 + 1];
        float px[4] = {a0.x, a0.z, a1.x, a1.z};
        float py[4] = {a0.y, a0.w, a1.y, a1.w};
        float qx[4] = {b0.x, b0.z, b1.x, b1.z};
        float qy[4] = {b0.y, b0.w, b1.y, b1.w};
        float inter = sh_inter(px, py, qx, qy);
        float ai = boxes[i * 5 + 2] * boxes[i * 5 + 3];
        float aj = boxes[j * 5 + 2] * boxes[j * 5 + 3];
        float iou = inter / fmaxf(ai + aj - inter, FEPS);
        if (iou > THRESH) {
            int blk = i >> 6;
            atomicOr(&g_maskT[(size_t)j * CB + blk], 1ULL << (i & 63));
            atomicOr(&g_colsum[j], 1u << blk);
        }
    }
}

// ---------------------------------------------------------------------------
// Kernel 3: parallel Jacobi fixpoint of the greedy recurrence.
//   keep[j] = (j<n) && !exists i<j: keep[i] && M[i][j]
// Register-cached maskT words (first 2 per row; global fallback). Epilogue
// restores maskT/colsum/g_count to zero for the next graph replay.
// ---------------------------------------------------------------------------
__global__ void reduce_kernel(int n, float* __restrict__ out, int out_size) {
    __shared__ unsigned s_kept[64];
    __shared__ unsigned s_pref[64];
    __shared__ int s_changed[2];
    __shared__ int s_total;
    const int tid = threadIdx.x;
    const int j0 = tid, j1 = tid + RTPB;

    if (tid == 0) { g_count = 0; s_changed[0] = 0; s_changed[1] = 0; }

    if (tid < 64) {
        int base = tid * 32;
        unsigned w = 0u;
        if (base + 32 <= n) w = FULLM;
        else if (base < n) w = (1u << (n - base)) - 1u;
        s_kept[tid] = w;
    }

    const unsigned cs0 = (j0 < n) ? g_colsum[j0] : 0u;
    const unsigned cs1 = (j1 < n) ? g_colsum[j1] : 0u;

    // register-cache first two maskT words per row
    unsigned long long A0 = 0, A1 = 0, B0 = 0, B1 = 0;
    int ab0 = -1, ab1 = -1, bb0 = -1, bb1 = -1;
    unsigned rest0 = 0, rest1 = 0;
    {
        unsigned s = cs0;
        if (s) { ab0 = __ffs(s) - 1; A0 = g_maskT[(size_t)j0 * CB + ab0]; s &= s - 1;
            if (s) { ab1 = __ffs(s) - 1; A1 = g_maskT[(size_t)j0 * CB + ab1]; s &= s - 1; }
            rest0 = s;
        }
        s = cs1;
        if (s) { bb0 = __ffs(s) - 1; B0 = g_maskT[(size_t)j1 * CB + bb0]; s &= s - 1;
            if (s) { bb1 = __ffs(s) - 1; B1 = g_maskT[(size_t)j1 * CB + bb1]; s &= s - 1; }
            rest1 = s;
        }
    }
    __syncthreads();

    int cur = 0;
    for (int iter = 0; iter < n; iter++) {
        bool k0, k1;
        {
            bool sup = false;
            if (ab0 >= 0) {
                unsigned long long kw = ((unsigned long long)s_kept[ab0 * 2 + 1] << 32)
                                        | (unsigned long long)s_kept[ab0 * 2];
                sup = (A0 & kw) != 0ULL;
            }
            if (!sup && ab1 >= 0) {
                unsigned long long kw = ((unsigned long long)s_kept[ab1 * 2 + 1] << 32)
                                        | (unsigned long long)s_kept[ab1 * 2];
                sup = (A1 & kw) != 0ULL;
            }
            unsigned s = rest0;
            while (!sup && s) {
                int blk = __ffs(s) - 1; s &= s - 1;
                unsigned long long m = g_maskT[(size_t)j0 * CB + blk];
                unsigned long long kw = ((unsigned long long)s_kept[blk * 2 + 1] << 32)
                                        | (unsigned long long)s_kept[blk * 2];
                sup = (m & kw) != 0ULL;
            }
            k0 = (j0 < n) && !sup;
        }
        {
            bool sup = false;
            if (bb0 >= 0) {
                unsigned long long kw = ((unsigned long long)s_kept[bb0 * 2 + 1] << 32)
                                        | (unsigned long long)s_kept[bb0 * 2];
                sup = (B0 & kw) != 0ULL;
            }
            if (!sup && bb1 >= 0) {
                unsigned long long kw = ((unsigned long long)s_kept[bb1 * 2 + 1] << 32)
                                        | (unsigned long long)s_kept[bb1 * 2];
                sup = (B1 & kw) != 0ULL;
            }
            unsigned s = rest1;
            while (!sup && s) {
                int blk = __ffs(s) - 1; s &= s - 1;
                unsigned long long m = g_maskT[(size_t)j1 * CB + blk];
                unsigned long long kw = ((unsigned long long)s_kept[blk * 2 + 1] << 32)
                                        | (unsigned long long)s_kept[blk * 2];
                sup = (m & kw) != 0ULL;
            }
            k1 = (j1 < n) && !sup;
        }
        __syncthreads();   // all reads of s_kept done
        unsigned b0 = __ballot_sync(FULLM, k0);
        unsigned b1 = __ballot_sync(FULLM, k1);
        int w = tid >> 5;
        if ((tid & 31) == 0) {
            if (s_kept[w] != b0)      { s_kept[w] = b0;      s_changed[cur] = 1; }
            if (s_kept[32 + w] != b1) { s_kept[32 + w] = b1; s_changed[cur] = 1; }
        }
        if (tid == 0) s_changed[cur ^ 1] = 0;   // pre-clear next flag
        __syncthreads();   // writes visible
        if (!s_changed[cur]) break;
        cur ^= 1;
    }

    // ---- emit ----
    if (tid == 0) {
        int acc = 0;
        for (int w = 0; w < 64; w++) { s_pref[w] = acc; acc += __popc(s_kept[w]); }
        s_total = acc;
    }
    __syncthreads();
    const int total = s_total;

#pragma unroll
    for (int rr = 0; rr < 2; rr++) {
        int j = tid + rr * RTPB;
        if (j < n) {
            unsigned w = s_kept[j >> 5];
            if ((w >> (j & 31)) & 1u) {
                int rank = (int)s_pref[j >> 5] + __popc(w & ((1u << (j & 31)) - 1u));
                if (rank < out_size) out[rank] = (float)j;
            }
        }
    }
    for (int k = total + tid; k < out_size; k += RTPB) out[k] = -1.0f;

    // ---- epilogue: restore scratch state to zero for next replay ----
    {
        unsigned s = cs0;
        while (s) { int blk = __ffs(s) - 1; s &= s - 1;
                    g_maskT[(size_t)j0 * CB + blk] = 0ULL; }
        if (j0 < n) g_colsum[j0] = 0u;
        s = cs1;
        while (s) { int blk = __ffs(s) - 1; s &= s - 1;
                    g_maskT[(size_t)j1 * CB + blk] = 0ULL; }
        if (j1 < n) g_colsum[j1] = 0u;
    }
}

// ---------------------------------------------------------------------------
extern "C" void kernel_launch(void* const* d_in, const int* in_sizes, int n_in,
                              void* d_out, int out_size) {
    const float* boxes = (const float*)d_in[0];
    int n = in_sizes[0] / 5;

    int rb = (n + TPB - 1) / TPB;          // 32 for n=2000
    int ntiles = rb * (rb + 1) / 2;        // 528
    int fblocks = (ntiles + TILES_PER_BLOCK - 1) / TILES_PER_BLOCK;  // 132

    filter_kernel<<<fblocks, FBLOCK>>>(boxes, n, rb, ntiles);

    clip_kernel<<<592, 128>>>(boxes);

    reduce_kernel<<<1, RTPB>>>(n, (float*)d_out, out_size);
}